// round 5
// baseline (speedup 1.0000x reference)
#include <cuda_runtime.h>
#include <math.h>
#include <stdint.h>

#define NN 100000
#define EE 300000
#define DD 256
#define FDIM 512
#define LL 5
#define GG 4000
#define NUM_BOND_C 2
#define BN_EPS 1e-5f

// ---------------- scratch (device globals: no allocation allowed) ----------------
__device__ float g_h[(size_t)NN * DD];
__device__ float g_agg[(size_t)NN * DD];
__device__ float g_tmp[(size_t)NN * FDIM];
__device__ float g_stat[2 * FDIM];
__device__ float g_ab[2 * DD];
__device__ float g_ssum[(size_t)GG * FDIM];
__device__ float g_cnt[GG];
__device__ float g_gfeat[(size_t)GG * FDIM];
__device__ float g_hid[(size_t)GG * (FDIM / 2)];
// pre-split weights (same [K,N] layout as inputs):
// w1[l] @ l*131072 | w2[l] @ 655360+l*131072 | feat @ 1310720 | head @ 1441792
#define WT_TOTAL 1572864
__device__ float g_w_hi[WT_TOTAL];
__device__ float g_w_lo[WT_TOTAL];

__device__ __forceinline__ float softplus_f(float x) {
    return fmaxf(x, 0.0f) + log1pf(expf(-fabsf(x)));
}

__device__ __forceinline__ void red_add_v4(float* p, float x, float y, float z, float w) {
    asm volatile("red.global.add.v4.f32 [%0], {%1,%2,%3,%4};"
                 :: "l"(p), "f"(x), "f"(y), "f"(z), "f"(w) : "memory");
}
__device__ __forceinline__ void red_add_f32(float* p, float v) {
    asm volatile("red.global.add.f32 [%0], %1;" :: "l"(p), "f"(v) : "memory");
}

// ---------------- tf32 helpers ----------------
__device__ __forceinline__ void split_tf32(float x, uint32_t& hi, uint32_t& lo) {
    uint32_t h = __float_as_uint(x) & 0xffffe000u;
    hi = h;
    lo = __float_as_uint(x - __uint_as_float(h));
}

__device__ __forceinline__ void mma8(float* c, const uint32_t* a, uint32_t b0, uint32_t b1) {
    asm volatile(
        "mma.sync.aligned.m16n8k8.row.col.f32.tf32.tf32.f32 "
        "{%0,%1,%2,%3},{%4,%5,%6,%7},{%8,%9},{%0,%1,%2,%3};"
        : "+f"(c[0]), "+f"(c[1]), "+f"(c[2]), "+f"(c[3])
        : "r"(a[0]), "r"(a[1]), "r"(a[2]), "r"(a[3]), "r"(b0), "r"(b1));
}

__device__ __forceinline__ void cpa16(void* dst, const void* src, int srcBytes) {
    uint32_t d = (uint32_t)__cvta_generic_to_shared(dst);
    asm volatile("cp.async.cg.shared.global [%0], [%1], 16, %2;"
                 :: "r"(d), "l"(src), "r"(srcBytes) : "memory");
}
__device__ __forceinline__ void cpa16f(void* dst, const void* src) {
    uint32_t d = (uint32_t)__cvta_generic_to_shared(dst);
    asm volatile("cp.async.cg.shared.global [%0], [%1], 16;"
                 :: "r"(d), "l"(src) : "memory");
}
__device__ __forceinline__ void cp_commit() {
    asm volatile("cp.async.commit_group;" ::: "memory");
}
__device__ __forceinline__ void cp_wait1() {
    asm volatile("cp.async.wait_group 1;" ::: "memory");
}

// ---------------- weight prep: elementwise tf32 split ----------------
__global__ void split_kernel(const float* __restrict__ W, float* __restrict__ hi,
                             float* __restrict__ lo, int n) {
    int idx = blockIdx.x * blockDim.x + threadIdx.x;
    if (idx >= n) return;
    float v = W[idx];
    uint32_t h = __float_as_uint(v) & 0xffffe000u;
    hi[idx] = __uint_as_float(h);
    lo[idx] = v - __uint_as_float(h);
}

// ---------------- init: h = x_emb1[atomics] + pos @ x_emb2_w + b ----------------
__global__ void init_h_kernel(const int* __restrict__ atomics,
                              const float* __restrict__ pos,
                              const float* __restrict__ emb1,
                              const float* __restrict__ w2,
                              const float* __restrict__ b2,
                              float* __restrict__ h) {
    size_t idx = (size_t)blockIdx.x * blockDim.x + threadIdx.x;
    if (idx >= (size_t)NN * DD) return;
    int i = (int)(idx / DD);
    int d = (int)(idx & (DD - 1));
    float p0 = pos[i * 3 + 0], p1 = pos[i * 3 + 1], p2 = pos[i * 3 + 2];
    float v = emb1[(size_t)atomics[i] * DD + d];
    v += p0 * w2[d] + p1 * w2[DD + d] + p2 * w2[2 * DD + d] + b2[d];
    h[idx] = v;
}

__global__ void agg_init_kernel(const float* __restrict__ h,
                                const float* __restrict__ emb_self,
                                float* __restrict__ agg) {
    size_t idx = (size_t)blockIdx.x * blockDim.x + threadIdx.x;
    if (idx >= (size_t)NN * DD / 4) return;
    int d4 = (int)(idx & (DD / 4 - 1)) * 4;
    float4 hv = *((const float4*)h + idx);
    float4 ev = *(const float4*)(emb_self + d4);
    *((float4*)agg + idx) = make_float4(hv.x + ev.x, hv.y + ev.y, hv.z + ev.z, hv.w + ev.w);
}

__global__ void scatter_edges_kernel(const float* __restrict__ h,
                                     const int* __restrict__ edge_index,
                                     const int* __restrict__ edge_attr,
                                     const float* __restrict__ emb,
                                     float* __restrict__ agg) {
    int e = blockIdx.x * (blockDim.x >> 5) + (threadIdx.x >> 5);
    if (e >= EE) return;
    int lane = threadIdx.x & 31;
    int s = edge_index[e];
    int t = edge_index[EE + e];
    const float* hs = h + (size_t)s * DD;
    const float* eb = emb + (size_t)edge_attr[e] * DD;
    float* ag = agg + (size_t)t * DD;
#pragma unroll
    for (int half = 0; half < 2; half++) {
        int c = lane * 4 + half * 128;
        float4 hv = *(const float4*)(hs + c);
        float4 ev = *(const float4*)(eb + c);
        red_add_v4(ag + c, hv.x + ev.x, hv.y + ev.y, hv.z + ev.z, hv.w + ev.w);
    }
}

// ---------------- tf32x3 tensor-core GEMM, 3-stage cp.async pipeline ----------------
// C[M,Nc] = act(A[M,K] @ B[K,Nc] + bias); B pre-split hi/lo ([K,N] layout).
// 128x128x16 block tile, 256 threads = 8 warps (4x2), warp tile 32x64.
// smem (floats): As[3][128][20] @0 (7680) | Bh[3][16][136] @7680 (6528) | Bl @14208 (6528)
#define SM_AS(s, m, k) smp[(s) * 2560 + (m) * 20 + (k)]
#define SM_BH(s, k, n) smp[7680 + (s) * 2176 + (k) * 136 + (n)]
#define SM_BL(s, k, n) smp[14208 + (s) * 2176 + (k) * 136 + (n)]
#define GEMM_SMEM_BYTES (20736 * 4)

__global__ __launch_bounds__(256, 2)
void gemm_tf32(const float* __restrict__ A, const float* __restrict__ Bhi,
               const float* __restrict__ Blo, const float* __restrict__ bias,
               float* __restrict__ C, int M, int K, int Nc, int act,
               float* __restrict__ stat) {
    extern __shared__ float smp[];

    const int tid = threadIdx.x;
    const int lane = tid & 31;
    const int w = tid >> 5;
    const int g = lane >> 2;
    const int t = lane & 3;
    const int warp_m = (w >> 1) * 32;
    const int warp_n = (w & 1) * 64;
    const int brow = blockIdx.y * 128;
    const int bcol = blockIdx.x * 128;

    // fill mappings: A chunks c = tid*2 + {0,1} over 512; B chunks likewise
    const int ac0 = tid * 2;
    const int a_row0 = ac0 >> 2, a_k0 = (ac0 & 3) * 4;
    const int a_row1 = (ac0 + 1) >> 2, a_k1 = ((ac0 + 1) & 3) * 4;
    const bool a_ok0 = (brow + a_row0) < M;
    const bool a_ok1 = (brow + a_row1) < M;
    const float* Ag0 = A + (size_t)(a_ok0 ? brow + a_row0 : 0) * K + a_k0;
    const float* Ag1 = A + (size_t)(a_ok1 ? brow + a_row1 : 0) * K + a_k1;

    const int b_k0 = ac0 >> 5, b_n0 = (ac0 & 31) * 4;
    const int b_k1 = (ac0 + 1) >> 5, b_n1 = ((ac0 + 1) & 31) * 4;
    const float* Bh0 = Bhi + (size_t)b_k0 * Nc + bcol + b_n0;
    const float* Bh1 = Bhi + (size_t)b_k1 * Nc + bcol + b_n1;
    const float* Bl0 = Blo + (size_t)b_k0 * Nc + bcol + b_n0;
    const float* Bl1 = Blo + (size_t)b_k1 * Nc + bcol + b_n1;

    float acc[2][8][4];
#pragma unroll
    for (int mt = 0; mt < 2; mt++)
#pragma unroll
        for (int nt = 0; nt < 8; nt++)
#pragma unroll
            for (int q = 0; q < 4; q++) acc[mt][nt][q] = 0.0f;

    const int T = K >> 4;

#define PREFETCH(stage, buf)                                                      \
    do {                                                                          \
        const int ko_ = (stage) << 4;                                             \
        cpa16(&SM_AS(buf, a_row0, a_k0), Ag0 + ko_, a_ok0 ? 16 : 0);              \
        cpa16(&SM_AS(buf, a_row1, a_k1), Ag1 + ko_, a_ok1 ? 16 : 0);              \
        cpa16f(&SM_BH(buf, b_k0, b_n0), Bh0 + (size_t)ko_ * Nc);                  \
        cpa16f(&SM_BH(buf, b_k1, b_n1), Bh1 + (size_t)ko_ * Nc);                  \
        cpa16f(&SM_BL(buf, b_k0, b_n0), Bl0 + (size_t)ko_ * Nc);                  \
        cpa16f(&SM_BL(buf, b_k1, b_n1), Bl1 + (size_t)ko_ * Nc);                  \
    } while (0)

    PREFETCH(0, 0);
    cp_commit();
    PREFETCH(1, 1);
    cp_commit();

    int buf = 0;
    for (int s = 0; s < T; s++) {
        cp_wait1();
        __syncthreads();
        if (s + 2 < T) {
            int nb = buf == 0 ? 2 : buf - 1;  // (s+2)%3
            PREFETCH(s + 2, nb);
        }
        cp_commit();  // always commit: keeps wait_group accounting uniform

#pragma unroll
        for (int kk = 0; kk < 16; kk += 8) {
            uint32_t ah[2][4], al[2][4];
#pragma unroll
            for (int mt = 0; mt < 2; mt++) {
                const int mr = warp_m + mt * 16 + g;
                split_tf32(SM_AS(buf, mr, kk + t), ah[mt][0], al[mt][0]);
                split_tf32(SM_AS(buf, mr + 8, kk + t), ah[mt][1], al[mt][1]);
                split_tf32(SM_AS(buf, mr, kk + t + 4), ah[mt][2], al[mt][2]);
                split_tf32(SM_AS(buf, mr + 8, kk + t + 4), ah[mt][3], al[mt][3]);
            }
#pragma unroll
            for (int nt = 0; nt < 8; nt++) {
                const int n = warp_n + nt * 8 + g;
                uint32_t bh0 = __float_as_uint(SM_BH(buf, kk + t, n));
                uint32_t bh1 = __float_as_uint(SM_BH(buf, kk + t + 4, n));
                uint32_t bl0 = __float_as_uint(SM_BL(buf, kk + t, n));
                uint32_t bl1 = __float_as_uint(SM_BL(buf, kk + t + 4, n));
#pragma unroll
                for (int mt = 0; mt < 2; mt++) {
                    mma8(acc[mt][nt], ah[mt], bh0, bh1);
                    mma8(acc[mt][nt], ah[mt], bl0, bl1);
                    mma8(acc[mt][nt], al[mt], bh0, bh1);
                }
            }
        }
        buf = buf == 2 ? 0 : buf + 1;
    }

    // ---------------- epilogue ----------------
    const bool do_stats = (stat != nullptr);
    float csum[16], csq[16];
    if (do_stats) {
#pragma unroll
        for (int i = 0; i < 16; i++) { csum[i] = 0.f; csq[i] = 0.f; }
    }

#pragma unroll
    for (int mt = 0; mt < 2; mt++) {
        const int r0 = brow + warp_m + mt * 16 + g;
#pragma unroll
        for (int nt = 0; nt < 8; nt++) {
            const int col = bcol + warp_n + nt * 8 + t * 2;
            const float b0v = bias[col];
            const float b1v = bias[col + 1];
            float v0 = acc[mt][nt][0] + b0v;
            float v1 = acc[mt][nt][1] + b1v;
            float v2 = acc[mt][nt][2] + b0v;
            float v3 = acc[mt][nt][3] + b1v;
            if (act) {
                v0 = softplus_f(v0); v1 = softplus_f(v1);
                v2 = softplus_f(v2); v3 = softplus_f(v3);
            }
            if (r0 < M) {
                *(float2*)&C[(size_t)r0 * Nc + col] = make_float2(v0, v1);
                if (do_stats) {
                    csum[nt * 2] += v0; csq[nt * 2] += v0 * v0;
                    csum[nt * 2 + 1] += v1; csq[nt * 2 + 1] += v1 * v1;
                }
            }
            if (r0 + 8 < M) {
                *(float2*)&C[(size_t)(r0 + 8) * Nc + col] = make_float2(v2, v3);
                if (do_stats) {
                    csum[nt * 2] += v2; csq[nt * 2] += v2 * v2;
                    csum[nt * 2 + 1] += v3; csq[nt * 2 + 1] += v3 * v3;
                }
            }
        }
    }

    if (do_stats) {
#pragma unroll
        for (int i = 0; i < 16; i++) {
            float sv = csum[i], qv = csq[i];
            sv += __shfl_xor_sync(0xffffffffu, sv, 4);
            sv += __shfl_xor_sync(0xffffffffu, sv, 8);
            sv += __shfl_xor_sync(0xffffffffu, sv, 16);
            qv += __shfl_xor_sync(0xffffffffu, qv, 4);
            qv += __shfl_xor_sync(0xffffffffu, qv, 8);
            qv += __shfl_xor_sync(0xffffffffu, qv, 16);
            if (g == 0) {
                const int col = bcol + warp_n + (i >> 1) * 8 + t * 2 + (i & 1);
                red_add_f32(&stat[col], sv);
                red_add_f32(&stat[Nc + col], qv);
            }
        }
    }
}

// ---------------- BN ----------------
__global__ void zero_kernel(float* __restrict__ p, size_t n) {
    size_t idx = (size_t)blockIdx.x * blockDim.x + threadIdx.x;
    if (idx < n) p[idx] = 0.0f;
}

__global__ void bn_finalize_kernel(const float* __restrict__ stat,
                                   const float* __restrict__ gamma,
                                   const float* __restrict__ beta,
                                   float* __restrict__ ab) {
    int d = threadIdx.x;
    float mean = stat[d] * (1.0f / NN);
    float var = stat[DD + d] * (1.0f / NN) - mean * mean;
    float inv = rsqrtf(var + BN_EPS);
    float a = gamma[d] * inv;
    ab[d] = a;
    ab[DD + d] = beta[d] - mean * a;
}

__global__ void bn_apply_agg_kernel(float* __restrict__ h, const float* __restrict__ ab,
                                    const float* __restrict__ emb_next,
                                    float* __restrict__ agg, int act) {
    size_t idx = (size_t)blockIdx.x * blockDim.x + threadIdx.x;
    if (idx >= (size_t)NN * DD / 4) return;
    int d4 = (int)(idx & (DD / 4 - 1)) * 4;
    float4 v = *((float4*)h + idx);
    float4 a = *(const float4*)(ab + d4);
    float4 b = *(const float4*)(ab + DD + d4);
    v.x = v.x * a.x + b.x;
    v.y = v.y * a.y + b.y;
    v.z = v.z * a.z + b.z;
    v.w = v.w * a.w + b.w;
    if (act) {
        v.x = softplus_f(v.x);
        v.y = softplus_f(v.y);
        v.z = softplus_f(v.z);
        v.w = softplus_f(v.w);
    }
    *((float4*)h + idx) = v;
    if (agg) {
        float4 e = *(const float4*)(emb_next + d4);
        *((float4*)agg + idx) = make_float4(v.x + e.x, v.y + e.y, v.z + e.z, v.w + e.w);
    }
}

// ---------------- pooling ----------------
__global__ void pool_count_kernel(const int* __restrict__ batch, float* __restrict__ cnt) {
    int i = blockIdx.x * blockDim.x + threadIdx.x;
    if (i >= NN) return;
    atomicAdd(&cnt[batch[i]], 1.0f);
}

__global__ void pool_sum_kernel(const float* __restrict__ feat,
                                const int* __restrict__ batch,
                                float* __restrict__ ssum) {
    size_t idx = (size_t)blockIdx.x * blockDim.x + threadIdx.x;
    const int CH = FDIM / 4;
    const size_t nchunks = (NN + 7) / 8;
    if (idx >= nchunks * CH) return;
    int f4 = (int)(idx & (CH - 1)) * 4;
    int i0 = (int)(idx / CH) * 8;
    int cur = batch[i0];
    float4 acc = make_float4(0.f, 0.f, 0.f, 0.f);
#pragma unroll
    for (int r = 0; r < 8; r++) {
        int i = i0 + r;
        if (i >= NN) break;
        int b = batch[i];
        if (b != cur) {
            red_add_v4(&ssum[(size_t)cur * FDIM + f4], acc.x, acc.y, acc.z, acc.w);
            acc = make_float4(0.f, 0.f, 0.f, 0.f);
            cur = b;
        }
        float4 v = *(const float4*)(feat + (size_t)i * FDIM + f4);
        acc.x += v.x; acc.y += v.y; acc.z += v.z; acc.w += v.w;
    }
    red_add_v4(&ssum[(size_t)cur * FDIM + f4], acc.x, acc.y, acc.z, acc.w);
}

__global__ void gfeat_kernel(const float* __restrict__ ssum, const float* __restrict__ cnt,
                             float* __restrict__ gfeat) {
    size_t idx = (size_t)blockIdx.x * blockDim.x + threadIdx.x;
    if (idx >= (size_t)GG * FDIM) return;
    int g = (int)(idx / FDIM);
    gfeat[idx] = ssum[idx] / fmaxf(cnt[g], 1.0f);
}

__global__ void head_out_kernel(const float* __restrict__ hid, const float* __restrict__ w2,
                                const float* __restrict__ b2, float* __restrict__ out) {
    int g = blockIdx.x * (blockDim.x >> 5) + (threadIdx.x >> 5);
    if (g >= GG) return;
    int lane = threadIdx.x & 31;
    const float* hr = hid + (size_t)g * (FDIM / 2);
    float s = 0.f;
#pragma unroll
    for (int k = lane; k < FDIM / 2; k += 32) s += hr[k] * w2[k];
#pragma unroll
    for (int o = 16; o; o >>= 1) s += __shfl_down_sync(0xffffffffu, s, o);
    if (lane == 0) out[g] = s + b2[0];
}

// ---------------- host launch ----------------
static inline void launch_gemm(const float* A, const float* Bhi, const float* Blo,
                               const float* bias, float* C,
                               int M, int K, int Nc, int act, float* stat) {
    dim3 grid(Nc / 128, (M + 127) / 128);
    gemm_tf32<<<grid, 256, GEMM_SMEM_BYTES>>>(A, Bhi, Blo, bias, C, M, K, Nc, act, stat);
}

extern "C" void kernel_launch(void* const* d_in, const int* in_sizes, int n_in,
                              void* d_out, int out_size) {
    const int* atomics = (const int*)d_in[0];
    const float* pos = (const float*)d_in[1];
    const int* edge_index = (const int*)d_in[2];
    const int* edge_attr = (const int*)d_in[3];
    const int* batch = (const int*)d_in[4];
    const float* x_emb1 = (const float*)d_in[5];
    const float* x_emb2_w = (const float*)d_in[6];
    const float* x_emb2_b = (const float*)d_in[7];
    const float* edge_emb = (const float*)d_in[8];
    const float* mlp_w1 = (const float*)d_in[9];
    const float* mlp_b1 = (const float*)d_in[10];
    const float* mlp_w2 = (const float*)d_in[11];
    const float* mlp_b2 = (const float*)d_in[12];
    const float* bn_gamma = (const float*)d_in[13];
    const float* bn_beta = (const float*)d_in[14];
    const float* feat_w = (const float*)d_in[15];
    const float* feat_b = (const float*)d_in[16];
    const float* head_w1 = (const float*)d_in[17];
    const float* head_b1 = (const float*)d_in[18];
    const float* head_w2 = (const float*)d_in[19];
    const float* head_b2 = (const float*)d_in[20];
    float* out = (float*)d_out;

    float *h, *agg, *tmp, *stat, *ab, *ssum, *cnt, *gfeat, *hid, *whi, *wlo;
    cudaGetSymbolAddress((void**)&h, g_h);
    cudaGetSymbolAddress((void**)&agg, g_agg);
    cudaGetSymbolAddress((void**)&tmp, g_tmp);
    cudaGetSymbolAddress((void**)&stat, g_stat);
    cudaGetSymbolAddress((void**)&ab, g_ab);
    cudaGetSymbolAddress((void**)&ssum, g_ssum);
    cudaGetSymbolAddress((void**)&cnt, g_cnt);
    cudaGetSymbolAddress((void**)&gfeat, g_gfeat);
    cudaGetSymbolAddress((void**)&hid, g_hid);
    cudaGetSymbolAddress((void**)&whi, g_w_hi);
    cudaGetSymbolAddress((void**)&wlo, g_w_lo);

    cudaFuncSetAttribute(gemm_tf32, cudaFuncAttributeMaxDynamicSharedMemorySize,
                         GEMM_SMEM_BYTES);

    const size_t ND = (size_t)NN * DD;
    const size_t ND4 = ND / 4;
    const int EL = 256;

    // ---- weight prep: split hi/lo (contiguous input arrays) ----
    split_kernel<<<(655360 + EL - 1) / EL, EL>>>(mlp_w1, whi, wlo, 655360);
    split_kernel<<<(655360 + EL - 1) / EL, EL>>>(mlp_w2, whi + 655360, wlo + 655360, 655360);
    split_kernel<<<(131072 + EL - 1) / EL, EL>>>(feat_w, whi + 1310720, wlo + 1310720, 131072);
    split_kernel<<<(131072 + EL - 1) / EL, EL>>>(head_w1, whi + 1441792, wlo + 1441792, 131072);

    init_h_kernel<<<(unsigned)((ND + EL - 1) / EL), EL>>>(atomics, pos, x_emb1, x_emb2_w,
                                                          x_emb2_b, h);
    {
        const float* emb_self0 =
            edge_emb + (size_t)0 * NUM_BOND_C * DD + (size_t)(NUM_BOND_C - 1) * DD;
        agg_init_kernel<<<(unsigned)((ND4 + EL - 1) / EL), EL>>>(h, emb_self0, agg);
    }

    for (int l = 0; l < LL; l++) {
        const float* emb_l = edge_emb + (size_t)l * NUM_BOND_C * DD;

        scatter_edges_kernel<<<(EE + 7) / 8, 256>>>(h, edge_index, edge_attr, emb_l, agg);

        // tmp = softplus(agg @ W1 + b1)   [N, 512]
        launch_gemm(agg, whi + (size_t)l * 131072, wlo + (size_t)l * 131072,
                    mlp_b1 + (size_t)l * 2 * DD, tmp, NN, DD, 2 * DD, 1, nullptr);

        zero_kernel<<<1, 512>>>(stat, 2 * DD);
        // h = tmp @ W2 + b2  (+ BN stats)   [N, 256]
        launch_gemm(tmp, whi + 655360 + (size_t)l * 131072, wlo + 655360 + (size_t)l * 131072,
                    mlp_b2 + (size_t)l * DD, h, NN, 2 * DD, DD, 0, stat);

        bn_finalize_kernel<<<1, 256>>>(stat, bn_gamma + (size_t)l * DD,
                                       bn_beta + (size_t)l * DD, ab);

        if (l < LL - 1) {
            const float* emb_self_next =
                edge_emb + (size_t)(l + 1) * NUM_BOND_C * DD + (size_t)(NUM_BOND_C - 1) * DD;
            bn_apply_agg_kernel<<<(unsigned)((ND4 + EL - 1) / EL), EL>>>(h, ab, emb_self_next,
                                                                         agg, 1);
        } else {
            bn_apply_agg_kernel<<<(unsigned)((ND4 + EL - 1) / EL), EL>>>(h, ab, nullptr,
                                                                         nullptr, 0);
        }
    }

    // feat = h @ feat_w + feat_b
    launch_gemm(h, whi + 1310720, wlo + 1310720, feat_b, tmp, NN, DD, FDIM, 0, nullptr);

    // global mean pool
    zero_kernel<<<(unsigned)(((size_t)GG * FDIM + EL - 1) / EL), EL>>>(ssum, (size_t)GG * FDIM);
    zero_kernel<<<(GG + EL - 1) / EL, EL>>>(cnt, GG);
    pool_count_kernel<<<(NN + EL - 1) / EL, EL>>>(batch, cnt);
    {
        size_t total = ((NN + 7) / 8) * (size_t)(FDIM / 4);
        pool_sum_kernel<<<(unsigned)((total + EL - 1) / EL), EL>>>(tmp, batch, ssum);
    }
    gfeat_kernel<<<(unsigned)(((size_t)GG * FDIM + EL - 1) / EL), EL>>>(ssum, cnt, gfeat);

    // hid = softplus(gfeat @ head_w1 + head_b1)
    launch_gemm(gfeat, whi + 1441792, wlo + 1441792, head_b1, hid, GG, FDIM, FDIM / 2, 1,
                nullptr);
    head_out_kernel<<<(GG + 7) / 8, 256>>>(hid, head_w2, head_b2, out);
}